// round 4
// baseline (speedup 1.0000x reference)
#include <cuda_runtime.h>

#define N 384
#define D 512
#define NCLASS 32
#define MARGIN 0.5f
#define EPS 1e-6f
#define MAXM 96            // max members per class (binomial(384,1/32): mean 12)
#define BLK 384
#define NWARP (BLK / 32)

// Finalize scratch; zero-initialized at load, winner resets each launch.
__device__ float g_acc;
__device__ int   g_cnt;

__global__ __launch_bounds__(BLK) void triplet_class_kernel(
    const float* __restrict__ features,
    const int*   __restrict__ labels,
    const int*   __restrict__ levels,
    float*       __restrict__ out) {
    __shared__ float s_pd[MAXM * MAXM];   // class-local distance matrix (diag unused)
    __shared__ int   s_memb[MAXM];        // global row index per member
    __shared__ int   s_mlev[MAXM];        // level per member
    __shared__ float s_asum[MAXM];        // per-anchor hinge sum
    __shared__ int   s_wcnt[NWARP];       // ballot compaction per-warp counts
    __shared__ int   s_m, s_m0;
    __shared__ float s_block;

    const int c    = blockIdx.x;          // class id
    const int t    = threadIdx.x;
    const int wid  = t >> 5;
    const int lane = t & 31;

    if (t == 0) { s_m0 = 0; s_block = 0.0f; }
    if (t < MAXM) s_asum[t] = 0.0f;

    // ---- compact members of class c (warp-ballot scan, no serial atomics) ----
    const int my_lab = labels[t];
    const int my_lev = levels[t];
    const bool match = (my_lab == c);
    const unsigned bal = __ballot_sync(0xffffffffu, match);
    if (lane == 0) s_wcnt[wid] = __popc(bal);
    __syncthreads();

    int base = 0;
#pragma unroll
    for (int w = 0; w < NWARP; w++) base += (w < wid) ? s_wcnt[w] : 0;
    int m_total = 0;
#pragma unroll
    for (int w = 0; w < NWARP; w++) m_total += s_wcnt[w];

    if (match) {
        const int r = base + __popc(bal & ((1u << lane) - 1u));
        s_memb[r] = t;
        s_mlev[r] = my_lev;
        if (my_lev == 0) atomicAdd(&s_m0, 1);
    }
    if (t == 0) s_m = m_total;
    __syncthreads();

    const int m  = s_m;
    const int m0 = s_m0;
    const int m1 = m - m0;

    // ---- distances: warp per unordered pair (b < a), symmetric store ----
    const int npairs = m * (m - 1) / 2;
    for (int p = wid; p < npairs; p += NWARP) {
        // decode triangular index: p = a(a-1)/2 + b, b < a
        int a = (int)((1.0f + sqrtf(8.0f * (float)p + 1.0f)) * 0.5f);
        while (a * (a - 1) / 2 > p) a--;
        while ((a + 1) * a / 2 <= p) a++;
        const int b = p - a * (a - 1) / 2;

        const float4* __restrict__ fa = (const float4*)(features + s_memb[a] * D);
        const float4* __restrict__ fb = (const float4*)(features + s_memb[b] * D);
        float acc = 0.0f;
#pragma unroll
        for (int u = 0; u < 4; u++) {
            const int idx = u * 32 + lane;
            float4 x = fa[idx];
            float4 y = fb[idx];
            float d0 = x.x - y.x + EPS;   // torch pairwise_distance eps
            float d1 = x.y - y.y + EPS;
            float d2 = x.z - y.z + EPS;
            float d3 = x.w - y.w + EPS;
            acc = fmaf(d0, d0, acc);
            acc = fmaf(d1, d1, acc);
            acc = fmaf(d2, d2, acc);
            acc = fmaf(d3, d3, acc);
        }
#pragma unroll
        for (int o = 16; o; o >>= 1) acc += __shfl_xor_sync(0xffffffffu, acc, o);
        if (lane == 0) {
            const float d = sqrtf(acc);
            s_pd[a * MAXM + b] = d;
            s_pd[b * MAXM + a] = d;
        }
    }
    __syncthreads();

    // ---- hinge: thread handles (anchor a, positive j), loops negatives k ----
    for (int idx = t; idx < m * m; idx += BLK) {
        const int a = idx / m;
        const int j = idx - a * m;
        const int lev_a = s_mlev[a];
        if (j != a && s_mlev[j] == lev_a) {
            const float dij = s_pd[a * MAXM + j];
            float acc = 0.0f;
            for (int k = 0; k < m; k++) {
                if (k != a && s_mlev[k] != lev_a)
                    acc += fmaxf(dij - s_pd[a * MAXM + k] + MARGIN, 0.0f);
            }
            if (acc != 0.0f) atomicAdd(&s_asum[a], acc);
        }
    }
    __syncthreads();

    // ---- per-anchor normalization, class accumulate ----
    for (int a = t; a < m; a += BLK) {
        const int npos = ((s_mlev[a] == 0) ? m0 : m1) - 1;
        const int nneg = (s_mlev[a] == 0) ? m1 : m0;
        if (npos > 0 && nneg > 0)
            atomicAdd(&s_block, s_asum[a] / (float)(npos * nneg));
    }
    __syncthreads();

    // ---- finalize: 32 blocks, one atomic each, last block writes out ----
    if (t == 0) {
        atomicAdd(&g_acc, s_block * (1.0f / (float)N));
        __threadfence();
        if (atomicAdd(&g_cnt, 1) == NCLASS - 1) {
            g_cnt = 0;
            out[0] = atomicExch(&g_acc, 0.0f);   // read + reset for graph replay
        }
    }
}

extern "C" void kernel_launch(void* const* d_in, const int* in_sizes, int n_in,
                              void* d_out, int out_size) {
    const float* features = (const float*)d_in[0];
    const int*   labels   = (const int*)d_in[1];
    const int*   levels   = (const int*)d_in[2];
    float* out = (float*)d_out;

    triplet_class_kernel<<<NCLASS, BLK>>>(features, labels, levels, out);
}

// round 5
// speedup vs baseline: 1.3449x; 1.3449x over previous
#include <cuda_runtime.h>

#define N 384
#define D 512
#define MARGIN 0.5f
#define EPS 1e-6f
#define BLK 384
#define NWARP (BLK / 32)

// Finalize scratch; zero-initialized at load, winner resets each launch so
// graph replays start clean.
__device__ float g_acc;
__device__ int   g_cnt;

__global__ __launch_bounds__(BLK) void triplet_fused_kernel(
    const float* __restrict__ features,
    const int*   __restrict__ labels,
    const int*   __restrict__ levels,
    float*       __restrict__ out) {
    __shared__ float    s_dist[N];          // only same-label entries written/read
    __shared__ unsigned s_pos_mask[NWARP];  // per-chunk positive mask
    __shared__ unsigned s_neg_mask[NWARP];  // per-chunk negative mask
    __shared__ float    s_sum;

    const int i    = blockIdx.x;
    const int t    = threadIdx.x;
    const int wid  = t >> 5;
    const int lane = t & 31;

    if (t == 0) s_sum = 0.0f;

    // Broadcast loads (same address across block -> single L2 transaction)
    const int lab_i = labels[i];
    const int lev_i = levels[i];
    // Per-candidate loads, coalesced
    const int lab_t = labels[t];
    const int lev_t = levels[t];

    const bool same   = (t != i) && (lab_t == lab_i);
    const bool is_pos = same && (lev_t == lev_i);

    const unsigned bal_same = __ballot_sync(0xffffffffu, same);
    const unsigned bal_pos  = __ballot_sync(0xffffffffu, is_pos);
    if (lane == 0) {
        s_pos_mask[wid] = bal_pos;
        s_neg_mask[wid] = bal_same & ~bal_pos;
    }

    // ---- distances: warp w handles same-label candidates in its own chunk ----
    const float4* __restrict__ fi = (const float4*)(features + i * D);
    unsigned mm = bal_same;
    while (mm) {
        const int b = __ffs(mm) - 1;
        mm &= mm - 1;
        const int j = (wid << 5) + b;
        const float4* __restrict__ fj = (const float4*)(features + j * D);
        float acc = 0.0f;
#pragma unroll
        for (int u = 0; u < 4; u++) {
            const int idx = u * 32 + lane;     // coalesced per warp
            float4 a = fi[idx];
            float4 bb = fj[idx];
            float d0 = a.x - bb.x + EPS;        // torch pairwise_distance eps
            float d1 = a.y - bb.y + EPS;
            float d2 = a.z - bb.z + EPS;
            float d3 = a.w - bb.w + EPS;
            acc = fmaf(d0, d0, acc);
            acc = fmaf(d1, d1, acc);
            acc = fmaf(d2, d2, acc);
            acc = fmaf(d3, d3, acc);
        }
#pragma unroll
        for (int o = 16; o; o >>= 1) acc += __shfl_xor_sync(0xffffffffu, acc, o);
        if (lane == 0) s_dist[j] = sqrtf(acc);
    }
    __syncthreads();

    // ---- hinge: positive thread t walks the negative bitmasks ----
    float acc = 0.0f;
    if (is_pos) {
        const float dij = s_dist[t];
#pragma unroll
        for (int w = 0; w < NWARP; w++) {
            unsigned nm = s_neg_mask[w];
            while (nm) {
                const int b = __ffs(nm) - 1;
                nm &= nm - 1;
                acc += fmaxf(dij - s_dist[(w << 5) + b] + MARGIN, 0.0f);
            }
        }
    }
    if (acc != 0.0f) atomicAdd(&s_sum, acc);   // only ~6 threads hit this
    __syncthreads();

    // ---- finalize: counts from masks, one global atomic per block ----
    if (t == 0) {
        int npos = 0, nneg = 0;
#pragma unroll
        for (int w = 0; w < NWARP; w++) {
            npos += __popc(s_pos_mask[w]);
            nneg += __popc(s_neg_mask[w]);
        }
        float contrib = 0.0f;
        if (npos > 0 && nneg > 0)
            contrib = s_sum / (float)(npos * nneg) * (1.0f / (float)N);
        atomicAdd(&g_acc, contrib);
        __threadfence();
        if (atomicAdd(&g_cnt, 1) == (int)gridDim.x - 1) {
            g_cnt = 0;
            out[0] = atomicExch(&g_acc, 0.0f);  // read + reset for graph replay
        }
    }
}

extern "C" void kernel_launch(void* const* d_in, const int* in_sizes, int n_in,
                              void* d_out, int out_size) {
    const float* features = (const float*)d_in[0];
    const int*   labels   = (const int*)d_in[1];
    const int*   levels   = (const int*)d_in[2];
    float* out = (float*)d_out;

    triplet_fused_kernel<<<N, BLK>>>(features, labels, levels, out);
}

// round 6
// speedup vs baseline: 1.3488x; 1.0029x over previous
#include <cuda_runtime.h>

#define N 384
#define D 512
#define MARGIN 0.5f
#define EPS 1e-6f
#define BLK 384
#define NWARP (BLK / 32)

// Finalize scratch; zero-initialized at load, winner resets each launch so
// graph replays start clean.
__device__ float g_acc;
__device__ int   g_cnt;

__global__ __launch_bounds__(BLK) void triplet_fused_kernel(
    const float* __restrict__ features,
    const int*   __restrict__ labels,
    const int*   __restrict__ levels,
    float*       __restrict__ out) {
    __shared__ float    s_dist[N];           // only same-label entries written/read
    __shared__ unsigned s_same_mask[NWARP];
    __shared__ unsigned s_neg_mask[NWARP];
    __shared__ float    s_sum;

    const int i    = blockIdx.x;
    const int t    = threadIdx.x;
    const int wid  = t >> 5;
    const int lane = t & 31;

    // Prefetch anchor row into registers — independent of the label loads,
    // so both DRAM round-trips overlap instead of serializing.
    const float4* __restrict__ fi = (const float4*)(features + i * D);
    const float4 a0 = fi[lane];
    const float4 a1 = fi[32 + lane];
    const float4 a2 = fi[64 + lane];
    const float4 a3 = fi[96 + lane];

    const int lab_i = labels[i];     // broadcast
    const int lev_i = levels[i];
    const int lab_t = labels[t];     // coalesced
    const int lev_t = levels[t];

    const bool same   = (t != i) && (lab_t == lab_i);
    const bool is_pos = same && (lev_t == lev_i);

    const unsigned bal_same = __ballot_sync(0xffffffffu, same);
    const unsigned bal_pos  = __ballot_sync(0xffffffffu, is_pos);
    if (lane == 0) {
        s_same_mask[wid] = bal_same;
        s_neg_mask[wid]  = bal_same & ~bal_pos;
    }
    if (t == 0) s_sum = 0.0f;
    __syncthreads();

    // Decode all chunk masks into registers; every warp sees the full set.
    unsigned msk[NWARP];
    int nsame = 0;
#pragma unroll
    for (int w = 0; w < NWARP; w++) { msk[w] = s_same_mask[w]; nsame += __popc(msk[w]); }

    // ---- distances: ordinal o of the same-label set -> warps round-robin ----
    for (int o = wid; o < nsame; o += NWARP) {
        int w = 0, rem = o;
        while (true) {
            const int c = __popc(msk[w]);
            if (rem < c) break;
            rem -= c;
            w++;
        }
        const int j = (w << 5) + (__fns(msk[w], 0, rem + 1));

        const float4* __restrict__ fj = (const float4*)(features + j * D);
        const float4 b0 = fj[lane];
        const float4 b1 = fj[32 + lane];
        const float4 b2 = fj[64 + lane];
        const float4 b3 = fj[96 + lane];

        float acc = 0.0f;
        float d;
        d = a0.x - b0.x + EPS; acc = fmaf(d, d, acc);   // torch eps convention
        d = a0.y - b0.y + EPS; acc = fmaf(d, d, acc);
        d = a0.z - b0.z + EPS; acc = fmaf(d, d, acc);
        d = a0.w - b0.w + EPS; acc = fmaf(d, d, acc);
        d = a1.x - b1.x + EPS; acc = fmaf(d, d, acc);
        d = a1.y - b1.y + EPS; acc = fmaf(d, d, acc);
        d = a1.z - b1.z + EPS; acc = fmaf(d, d, acc);
        d = a1.w - b1.w + EPS; acc = fmaf(d, d, acc);
        d = a2.x - b2.x + EPS; acc = fmaf(d, d, acc);
        d = a2.y - b2.y + EPS; acc = fmaf(d, d, acc);
        d = a2.z - b2.z + EPS; acc = fmaf(d, d, acc);
        d = a2.w - b2.w + EPS; acc = fmaf(d, d, acc);
        d = a3.x - b3.x + EPS; acc = fmaf(d, d, acc);
        d = a3.y - b3.y + EPS; acc = fmaf(d, d, acc);
        d = a3.z - b3.z + EPS; acc = fmaf(d, d, acc);
        d = a3.w - b3.w + EPS; acc = fmaf(d, d, acc);
#pragma unroll
        for (int o2 = 16; o2; o2 >>= 1) acc += __shfl_xor_sync(0xffffffffu, acc, o2);
        if (lane == 0) s_dist[j] = sqrtf(acc);
    }
    __syncthreads();

    // ---- hinge: positive thread t walks the negative bitmasks (~6 iters) ----
    float acc = 0.0f;
    if (is_pos) {
        const float dij = s_dist[t];
#pragma unroll
        for (int w = 0; w < NWARP; w++) {
            unsigned nm = s_neg_mask[w];
            while (nm) {
                const int b = __ffs(nm) - 1;
                nm &= nm - 1;
                acc += fmaxf(dij - s_dist[(w << 5) + b] + MARGIN, 0.0f);
            }
        }
    }
    if (acc != 0.0f) atomicAdd(&s_sum, acc);   // only ~6 threads land here
    __syncthreads();

    // ---- finalize: counts from masks, one global atomic per block ----
    if (t == 0) {
        int nneg = 0;
#pragma unroll
        for (int w = 0; w < NWARP; w++) nneg += __popc(s_neg_mask[w]);
        const int npos = nsame - nneg;
        float contrib = 0.0f;
        if (npos > 0 && nneg > 0)
            contrib = s_sum / (float)(npos * nneg) * (1.0f / (float)N);
        atomicAdd(&g_acc, contrib);
        __threadfence();
        if (atomicAdd(&g_cnt, 1) == (int)gridDim.x - 1) {
            g_cnt = 0;
            out[0] = atomicExch(&g_acc, 0.0f);  // read + reset for graph replay
        }
    }
}

extern "C" void kernel_launch(void* const* d_in, const int* in_sizes, int n_in,
                              void* d_out, int out_size) {
    const float* features = (const float*)d_in[0];
    const int*   labels   = (const int*)d_in[1];
    const int*   levels   = (const int*)d_in[2];
    float* out = (float*)d_out;

    triplet_fused_kernel<<<N, BLK>>>(features, labels, levels, out);
}

// round 7
// speedup vs baseline: 1.6631x; 1.2330x over previous
#include <cuda_runtime.h>

#define N 384
#define D 512
#define MARGIN 0.5f
#define EPS 1e-6f
#define BLK 384
#define NWARP (BLK / 32)

// Finalize scratch; zero-initialized at load, winner resets each launch so
// graph replays start clean.
__device__ float g_acc;
__device__ int   g_cnt;

__global__ __launch_bounds__(BLK) void triplet_fused_kernel(
    const float* __restrict__ features,
    const int*   __restrict__ labels,
    const int*   __restrict__ levels,
    float*       __restrict__ out) {
    __shared__ float s_dist[N];     // only same-label entries written/read
    __shared__ int   s_same[N];     // compacted same-label indices
    __shared__ int   s_negl[N];     // compacted negative indices
    __shared__ int   s_wcnt[NWARP]; // per-warp same-label counts
    __shared__ int   s_wneg[NWARP]; // per-warp negative counts
    __shared__ float s_sum;

    const int i    = blockIdx.x;
    const int t    = threadIdx.x;
    const int wid  = t >> 5;
    const int lane = t & 31;

    if (t == 0) s_sum = 0.0f;

    const int lab_i = labels[i];     // broadcast: one L2 transaction
    const int lev_i = levels[i];
    const int lab_t = labels[t];     // coalesced
    const int lev_t = levels[t];

    const bool same   = (t != i) && (lab_t == lab_i);
    const bool is_pos = same && (lev_t == lev_i);
    const bool is_neg = same && !is_pos;

    const unsigned bal_same = __ballot_sync(0xffffffffu, same);
    const unsigned bal_neg  = __ballot_sync(0xffffffffu, is_neg);
    if (lane == 0) {
        s_wcnt[wid] = __popc(bal_same);
        s_wneg[wid] = __popc(bal_neg);
    }
    __syncthreads();

    // Register prefix over 12 warp counts (paid once, not per pair).
    int base_s = 0, base_n = 0, nsame = 0, nneg = 0;
#pragma unroll
    for (int w = 0; w < NWARP; w++) {
        const int cs = s_wcnt[w], cn = s_wneg[w];
        if (w < wid) { base_s += cs; base_n += cn; }
        nsame += cs;
        nneg  += cn;
    }
    if (same)   s_same[base_s + __popc(bal_same & ((1u << lane) - 1u))] = t;
    if (is_neg) s_negl[base_n + __popc(bal_neg  & ((1u << lane) - 1u))] = t;
    __syncthreads();

    // ---- distances: warps round-robin over the compacted list (balanced) ----
    const float4* __restrict__ fi = (const float4*)(features + i * D);
    for (int m = wid; m < nsame; m += NWARP) {
        const int j = s_same[m];
        const float4* __restrict__ fj = (const float4*)(features + j * D);
        float acc = 0.0f;
#pragma unroll
        for (int u = 0; u < 4; u++) {
            const int idx = u * 32 + lane;   // coalesced per warp, MLP=4
            float4 a = fi[idx];
            float4 b = fj[idx];
            float d0 = a.x - b.x + EPS;      // torch pairwise_distance eps
            float d1 = a.y - b.y + EPS;
            float d2 = a.z - b.z + EPS;
            float d3 = a.w - b.w + EPS;
            acc = fmaf(d0, d0, acc);
            acc = fmaf(d1, d1, acc);
            acc = fmaf(d2, d2, acc);
            acc = fmaf(d3, d3, acc);
        }
#pragma unroll
        for (int o = 16; o; o >>= 1) acc += __shfl_xor_sync(0xffffffffu, acc, o);
        if (lane == 0) s_dist[j] = sqrtf(acc);
    }
    __syncthreads();

    // ---- hinge: positive thread loops over ~6 compacted negatives ----
    float acc = 0.0f;
    if (is_pos) {
        const float dij = s_dist[t];
        for (int q = 0; q < nneg; q++) {
            acc += fmaxf(dij - s_dist[s_negl[q]] + MARGIN, 0.0f);
        }
    }
    if (acc != 0.0f) atomicAdd(&s_sum, acc);   // only ~6 threads land here
    __syncthreads();

    // ---- finalize: one global atomic per block, last block writes out ----
    if (t == 0) {
        const int npos = nsame - nneg;
        float contrib = 0.0f;
        if (npos > 0 && nneg > 0)
            contrib = s_sum / (float)(npos * nneg) * (1.0f / (float)N);
        atomicAdd(&g_acc, contrib);
        __threadfence();
        if (atomicAdd(&g_cnt, 1) == (int)gridDim.x - 1) {
            g_cnt = 0;
            out[0] = atomicExch(&g_acc, 0.0f);  // read + reset for graph replay
        }
    }
}

extern "C" void kernel_launch(void* const* d_in, const int* in_sizes, int n_in,
                              void* d_out, int out_size) {
    const float* features = (const float*)d_in[0];
    const int*   labels   = (const int*)d_in[1];
    const int*   levels   = (const int*)d_in[2];
    float* out = (float*)d_out;

    triplet_fused_kernel<<<N, BLK>>>(features, labels, levels, out);
}